// round 15
// baseline (speedup 1.0000x reference)
#include <cuda_runtime.h>
#include <math_constants.h>
#include <math.h>

// Problem constants (fixed shapes per reference)
#define T_TOK 4096
#define NC    4096            // span candidates
#define HD    1024            // hidden
#define WMAX  30
#define META  20
#define DSPAN 3092            // 3*HD + META
#define UHID  1024
#define NM    1024            // num_top_mentions
#define KA    50              // num_top_antecedents
#define NEGF  (-1e30f)

// ---------------- scratch (static device memory; no allocations) -------------
__device__ float g_tok_logits[T_TOK];
__device__ float g_span_emb[(size_t)NC * DSPAN];   // 50.6 MB
__device__ float g_U[(size_t)NC * UHID];           // 16.8 MB
__device__ float g_scores[NC];
__device__ int   g_order[NC];
__device__ int   g_sel[NC];
__device__ int   g_top_idx[NM];
__device__ float g_top_m[NM];
__device__ float g_G[(size_t)NM * DSPAN];          // 12.7 MB
__device__ float g_fast[(size_t)NM * NM];          // 4.2 MB

// ======================= OUTPUT-0 PIPELINE (round-7 verified exact) ==========

// ---------------- token logits: hidden @ w_attn + b_attn ---------------------
__global__ void k_token_logits(const float* __restrict__ hidden,
                               const float* __restrict__ w_attn,
                               const float* __restrict__ b_attn) {
    int warp = (blockIdx.x * blockDim.x + threadIdx.x) >> 5;
    int lane = threadIdx.x & 31;
    if (warp >= T_TOK) return;
    const float* row = hidden + (size_t)warp * HD;
    float acc = 0.f;
    for (int j = lane; j < HD; j += 32) acc += row[j] * w_attn[j];
    #pragma unroll
    for (int off = 16; off; off >>= 1) acc += __shfl_xor_sync(0xffffffffu, acc, off);
    if (lane == 0) g_tok_logits[warp] = acc + b_attn[0];
}

// -------- span embeddings: [h_start | h_end | width_emb | attended] ----------
__global__ void k_span_emb(const float* __restrict__ hidden,
                           const int* __restrict__ starts,
                           const int* __restrict__ widths,
                           const float* __restrict__ w_width) {
    int c = blockIdx.x;
    int s = starts[c], w = widths[c];
    int e = s + w, L = w + 1;            // span length <= 30
    __shared__ float wts[32];
    int tid = threadIdx.x;               // 128 threads
    if (tid < 32) {
        float l = (tid < L) ? g_tok_logits[s + tid] : -CUDART_INF_F;
        float mx = l;
        #pragma unroll
        for (int off = 16; off; off >>= 1) mx = fmaxf(mx, __shfl_xor_sync(0xffffffffu, mx, off));
        float p = (tid < L) ? expf(l - mx) : 0.f;
        float sum = p;
        #pragma unroll
        for (int off = 16; off; off >>= 1) sum += __shfl_xor_sync(0xffffffffu, sum, off);
        wts[tid] = p / sum;
    }
    __syncthreads();

    const float4* hs = (const float4*)(hidden + (size_t)s * HD);
    const float4* he = (const float4*)(hidden + (size_t)e * HD);
    float4 a0 = make_float4(0.f, 0.f, 0.f, 0.f), a1 = a0;
    for (int t = 0; t < L; t++) {
        float wt = wts[t];
        const float4* hr = (const float4*)(hidden + (size_t)(s + t) * HD);
        float4 v0 = hr[tid], v1 = hr[tid + 128];
        a0.x += wt * v0.x; a0.y += wt * v0.y; a0.z += wt * v0.z; a0.w += wt * v0.w;
        a1.x += wt * v1.x; a1.y += wt * v1.y; a1.z += wt * v1.z; a1.w += wt * v1.w;
    }
    float* out = g_span_emb + (size_t)c * DSPAN;
    ((float4*)out)[tid]            = hs[tid];
    ((float4*)out)[tid + 128]      = hs[tid + 128];
    ((float4*)(out + HD))[tid]       = he[tid];
    ((float4*)(out + HD))[tid + 128] = he[tid + 128];
    if (tid < META) out[2 * HD + tid] = w_width[w * META + tid];
    ((float4*)(out + 2 * HD + META))[tid]       = a0;
    ((float4*)(out + 2 * HD + META))[tid + 128] = a1;
}

// ---------------- tiled fp32 GEMM (NN) for the mention MLP -------------------
template<bool GATHER_A, bool RELU, bool BIAS>
__global__ __launch_bounds__(256) void k_gemm_nn(
    const float* __restrict__ A, const float* __restrict__ B,
    const float* __restrict__ bias, float* __restrict__ Cmat,
    int Mdim, int Ndim, int Kdim, const int* __restrict__ gatherA) {
    __shared__ float As[8][128];
    __shared__ float Bs[8][128];
    int tid = threadIdx.x;
    int m0 = blockIdx.y * 128, n0 = blockIdx.x * 128;
    int tx = tid & 15, ty = tid >> 4;
    float acc[8][8];
    #pragma unroll
    for (int i = 0; i < 8; i++)
        #pragma unroll
        for (int j = 0; j < 8; j++) acc[i][j] = 0.f;

    int arow = tid >> 1, aq = (tid & 1) * 4;
    int bk = tid >> 5, bq = (tid & 31) * 4;
    int agr = m0 + arow;
    bool a_valid = (agr < Mdim);
    const float* Aptr = A;
    if (a_valid) {
        int asrc = GATHER_A ? gatherA[agr] : agr;
        Aptr = A + (size_t)asrc * Kdim;
    }
    for (int k0 = 0; k0 < Kdim; k0 += 8) {
        float4 av = make_float4(0.f, 0.f, 0.f, 0.f);
        if (a_valid && (k0 + aq) < Kdim) av = *(const float4*)(Aptr + k0 + aq);
        As[aq + 0][arow] = av.x; As[aq + 1][arow] = av.y;
        As[aq + 2][arow] = av.z; As[aq + 3][arow] = av.w;
        float4 bv = make_float4(0.f, 0.f, 0.f, 0.f);
        if ((k0 + bk) < Kdim && (n0 + bq) < Ndim)
            bv = *(const float4*)(B + (size_t)(k0 + bk) * Ndim + n0 + bq);
        *(float4*)&Bs[bk][bq] = bv;
        __syncthreads();
        #pragma unroll
        for (int kk = 0; kk < 8; kk++) {
            float a[8], b[8];
            *(float4*)(a)     = *(const float4*)&As[kk][ty * 8];
            *(float4*)(a + 4) = *(const float4*)&As[kk][ty * 8 + 4];
            *(float4*)(b)     = *(const float4*)&Bs[kk][tx * 8];
            *(float4*)(b + 4) = *(const float4*)&Bs[kk][tx * 8 + 4];
            #pragma unroll
            for (int i = 0; i < 8; i++)
                #pragma unroll
                for (int j = 0; j < 8; j++) acc[i][j] += a[i] * b[j];
        }
        __syncthreads();
    }
    #pragma unroll
    for (int i = 0; i < 8; i++) {
        int r = m0 + ty * 8 + i;
        if (r >= Mdim) continue;
        #pragma unroll
        for (int j = 0; j < 8; j++) {
            int cc = n0 + tx * 8 + j;
            if (cc >= Ndim) continue;
            float v = acc[i][j];
            if (BIAS) v += bias[cc];
            if (RELU) v = fmaxf(v, 0.f);
            Cmat[(size_t)r * Ndim + cc] = v;
        }
    }
}

// -------- mention scores: dot(relu'd U row, w_u2) + b_u2 ---------------------
__global__ void k_mention_score(const float* __restrict__ w_u2,
                                const float* __restrict__ b_u2) {
    int c = blockIdx.x;
    int tid = threadIdx.x;   // 128 threads
    const float* row = g_U + (size_t)c * UHID;
    float acc = 0.f;
    for (int j = tid; j < UHID; j += 128) acc += row[j] * w_u2[j];
    #pragma unroll
    for (int off = 16; off; off >>= 1) acc += __shfl_xor_sync(0xffffffffu, acc, off);
    __shared__ float rs[4];
    if ((tid & 31) == 0) rs[tid >> 5] = acc;
    __syncthreads();
    if (tid == 0) g_scores[c] = rs[0] + rs[1] + rs[2] + rs[3] + b_u2[0];
}

// -------- bitonic argsort (descending score, ties -> lower index first) ------
__global__ void k_sort() {
    __shared__ float sv[NC];
    __shared__ int   si[NC];
    int tid = threadIdx.x;   // 1024
    for (int i = tid; i < NC; i += 1024) { sv[i] = g_scores[i]; si[i] = i; }
    __syncthreads();
    for (int k = 2; k <= NC; k <<= 1) {
        for (int j = k >> 1; j > 0; j >>= 1) {
            for (int i = tid; i < NC; i += 1024) {
                int ixj = i ^ j;
                if (ixj > i) {
                    bool dir = ((i & k) == 0);
                    float v1 = sv[i], v2 = sv[ixj];
                    int a1 = si[i], a2 = si[ixj];
                    bool i_later = (v1 < v2) || (v1 == v2 && a1 > a2);
                    if (i_later == dir) {
                        sv[i] = v2; si[i] = a2; sv[ixj] = v1; si[ixj] = a1;
                    }
                }
            }
            __syncthreads();
        }
    }
    for (int i = tid; i < NC; i += 1024) g_order[i] = si[i];
}

// -------- greedy non-crossing selection (single warp, early break) -----------
__global__ void k_greedy(const int* __restrict__ starts,
                         const int* __restrict__ widths) {
    __shared__ int le[T_TOK];   // latest_end
    __shared__ int es[T_TOK];   // earliest_start
    int lane = threadIdx.x;     // 32 threads
    for (int i = lane; i < T_TOK; i += 32) { le[i] = -1; es[i] = T_TOK; }
    for (int i = lane; i < NC; i += 32) g_sel[i] = 0;
    __syncwarp();
    int count = 0;
    for (int it = 0; it < NC; it++) {
        int ind = g_order[it];
        int s = starts[ind];
        int span = widths[ind];          // = e - s, 0..29
        int e = s + span;
        bool bad = false;
        if (lane < span) {
            if (le[s + 1 + lane] > e) bad = true;   // cross1 over (s, e]
            if (es[s + lane] < s)     bad = true;   // cross2 over [s, e)
        }
        unsigned anyb = __ballot_sync(0xffffffffu, bad);
        if (anyb == 0u) {
            if (lane == 0) {
                le[s] = max(le[s], e);
                es[e] = min(es[e], s);
                g_sel[ind] = 1;
            }
            count++;
            if (count == NM) break;
        }
        __syncwarp();
    }
}

// -------- compaction: selected indices ascending -> top_idx, top_m, out ------
__global__ void k_compact(float* __restrict__ out) {
    __shared__ int ps[1024];
    int tid = threadIdx.x;   // 1024
    int c4 = tid * 4;
    int f0 = g_sel[c4], f1 = g_sel[c4 + 1], f2 = g_sel[c4 + 2], f3 = g_sel[c4 + 3];
    int s = f0 + f1 + f2 + f3;
    ps[tid] = s;
    __syncthreads();
    for (int off = 1; off < 1024; off <<= 1) {
        int add = (tid >= off) ? ps[tid - off] : 0;
        __syncthreads();
        ps[tid] += add;
        __syncthreads();
    }
    int total = ps[1023];
    int pos = ps[tid] - s;
    if (f0) { if (pos < NM) g_top_idx[pos] = c4;     pos++; }
    if (f1) { if (pos < NM) g_top_idx[pos] = c4 + 1; pos++; }
    if (f2) { if (pos < NM) g_top_idx[pos] = c4 + 2; pos++; }
    if (f3) { if (pos < NM) g_top_idx[pos] = c4 + 3; pos++; }
    __syncthreads();
    if (tid >= total && tid < NM) g_top_idx[tid] = NC - 1;  // pad -> 4095
    __syncthreads();
    int ti = g_top_idx[tid];
    g_top_m[tid] = g_scores[ti];
    out[tid] = (float)ti;
}

// ================== DOWNSTREAM GEMMS: Kahan-compensated fp32 =================
// Goal: each dot ~1 ulp from the exact sum, so my-vs-ref deviation collapses
// to ref's own rounding. All steps via _rn intrinsics (no contraction, no
// fast-math reassociation).

// G = emb[top_idx] @ w_fast + b_fast.  64x64 tile, 256 thr, 4x4/thread.
__global__ __launch_bounds__(256) void k_gemm_g_kahan(
    const float* __restrict__ Afull /*span_emb*/, const float* __restrict__ B /*w_fast*/,
    const float* __restrict__ bias, float* __restrict__ Cmat /*G*/) {
    const int Kdim = DSPAN, Ndim = DSPAN;
    __shared__ float As[8][64];
    __shared__ float Bs[8][64];
    int tid = threadIdx.x;
    int m0 = blockIdx.y * 64, n0 = blockIdx.x * 64;
    int tx = tid & 15, ty = tid >> 4;
    float s[4][4], c[4][4];
    #pragma unroll
    for (int i = 0; i < 4; i++)
        #pragma unroll
        for (int j = 0; j < 4; j++) { s[i][j] = 0.f; c[i][j] = 0.f; }

    for (int k0 = 0; k0 < Kdim; k0 += 8) {
        // load A: 64 rows x 8 k (gathered)
        #pragma unroll
        for (int i = tid; i < 512; i += 256) {
            int kk = i & 7, m = i >> 3;
            int src = g_top_idx[m0 + m];
            float v = 0.f;
            if (k0 + kk < Kdim) v = Afull[(size_t)src * Kdim + k0 + kk];
            As[kk][m] = v;
        }
        // load B: 8 k x 64 n
        #pragma unroll
        for (int i = tid; i < 512; i += 256) {
            int kk = i >> 6, nn = i & 63;
            float v = 0.f;
            if (k0 + kk < Kdim && n0 + nn < Ndim)
                v = B[(size_t)(k0 + kk) * Ndim + n0 + nn];
            Bs[kk][nn] = v;
        }
        __syncthreads();
        #pragma unroll
        for (int kk = 0; kk < 8; kk++) {
            float a[4], b[4];
            #pragma unroll
            for (int i = 0; i < 4; i++) a[i] = As[kk][ty * 4 + i];
            #pragma unroll
            for (int j = 0; j < 4; j++) b[j] = Bs[kk][tx * 4 + j];
            #pragma unroll
            for (int i = 0; i < 4; i++)
                #pragma unroll
                for (int j = 0; j < 4; j++) {
                    float prod = __fmul_rn(a[i], b[j]);
                    float y = __fsub_rn(prod, c[i][j]);
                    float t = __fadd_rn(s[i][j], y);
                    c[i][j] = __fsub_rn(__fsub_rn(t, s[i][j]), y);
                    s[i][j] = t;
                }
        }
        __syncthreads();
    }
    #pragma unroll
    for (int i = 0; i < 4; i++) {
        int r = m0 + ty * 4 + i;
        #pragma unroll
        for (int j = 0; j < 4; j++) {
            int cc = n0 + tx * 4 + j;
            if (cc >= Ndim) continue;
            float dot = __fadd_rn(s[i][j], c[i][j]);
            Cmat[(size_t)r * Ndim + cc] = __fadd_rn(dot, bias[cc]);
        }
    }
}

// fast = (tm_i + tm_j) + G @ emb[top_idx]^T, masked (cc>=r) -> exact -1e30f.
__global__ __launch_bounds__(256) void k_gemm_fast_kahan(
    const float* __restrict__ A /*G*/, const float* __restrict__ Bfull /*span_emb*/,
    float* __restrict__ Cmat /*fast*/) {
    const int Kdim = DSPAN;
    __shared__ float As[8][64];
    __shared__ float Bs[8][64];
    int tid = threadIdx.x;
    int m0 = blockIdx.y * 64, n0 = blockIdx.x * 64;
    int tx = tid & 15, ty = tid >> 4;
    float s[4][4], c[4][4];
    #pragma unroll
    for (int i = 0; i < 4; i++)
        #pragma unroll
        for (int j = 0; j < 4; j++) { s[i][j] = 0.f; c[i][j] = 0.f; }

    for (int k0 = 0; k0 < Kdim; k0 += 8) {
        #pragma unroll
        for (int i = tid; i < 512; i += 256) {
            int kk = i & 7, m = i >> 3;
            float v = 0.f;
            if (k0 + kk < Kdim) v = A[(size_t)(m0 + m) * Kdim + k0 + kk];
            As[kk][m] = v;
        }
        #pragma unroll
        for (int i = tid; i < 512; i += 256) {
            int kk = i & 7, nn = i >> 3;
            int src = g_top_idx[n0 + nn];
            float v = 0.f;
            if (k0 + kk < Kdim) v = Bfull[(size_t)src * Kdim + k0 + kk];
            Bs[kk][nn] = v;
        }
        __syncthreads();
        #pragma unroll
        for (int kk = 0; kk < 8; kk++) {
            float a[4], b[4];
            #pragma unroll
            for (int i = 0; i < 4; i++) a[i] = As[kk][ty * 4 + i];
            #pragma unroll
            for (int j = 0; j < 4; j++) b[j] = Bs[kk][tx * 4 + j];
            #pragma unroll
            for (int i = 0; i < 4; i++)
                #pragma unroll
                for (int j = 0; j < 4; j++) {
                    float prod = __fmul_rn(a[i], b[j]);
                    float y = __fsub_rn(prod, c[i][j]);
                    float t = __fadd_rn(s[i][j], y);
                    c[i][j] = __fsub_rn(__fsub_rn(t, s[i][j]), y);
                    s[i][j] = t;
                }
        }
        __syncthreads();
    }
    #pragma unroll
    for (int i = 0; i < 4; i++) {
        int r = m0 + ty * 4 + i;
        float tmr = g_top_m[r];
        #pragma unroll
        for (int j = 0; j < 4; j++) {
            int cc = n0 + tx * 4 + j;
            float dot = __fadd_rn(s[i][j], c[i][j]);
            // ref association: ((tm_i + tm_j) + 0) + dot
            float v = __fadd_rn(__fadd_rn(tmr, g_top_m[cc]), dot);
            if (cc >= r) v = NEGF;
            Cmat[(size_t)r * NM + cc] = v;
        }
    }
}

// -------- per-row top-50 (lax.top_k semantics: desc, ties -> lowest index) ---
__global__ void k_topk(float* __restrict__ out) {
    int i = blockIdx.x;
    __shared__ float sv[NM];
    __shared__ float wvv[8];
    __shared__ int   wii[8];
    int tid = threadIdx.x;   // 256
    const float* row = g_fast + (size_t)i * NM;
    for (int j = tid; j < NM; j += 256) sv[j] = row[j];
    __syncthreads();
    float* out_ant  = out + NM;
    float* out_mask = out + NM + NM * KA;
    float* out_sc   = out + NM + 2 * NM * KA;
    for (int k = 0; k < KA; k++) {
        float bv = -CUDART_INF_F;
        int bi = NM;
        for (int j = tid; j < NM; j += 256) {
            float v = sv[j];
            if (v > bv || (v == bv && j < bi)) { bv = v; bi = j; }
        }
        #pragma unroll
        for (int off = 16; off; off >>= 1) {
            float ov = __shfl_down_sync(0xffffffffu, bv, off);
            int   oi = __shfl_down_sync(0xffffffffu, bi, off);
            if (ov > bv || (ov == bv && oi < bi)) { bv = ov; bi = oi; }
        }
        if ((tid & 31) == 0) { wvv[tid >> 5] = bv; wii[tid >> 5] = bi; }
        __syncthreads();
        if (tid < 32) {
            bv = (tid < 8) ? wvv[tid] : -CUDART_INF_F;
            bi = (tid < 8) ? wii[tid] : NM;
            #pragma unroll
            for (int off = 4; off; off >>= 1) {
                float ov = __shfl_down_sync(0xffffffffu, bv, off);
                int   oi = __shfl_down_sync(0xffffffffu, bi, off);
                if (ov > bv || (ov == bv && oi < bi)) { bv = ov; bi = oi; }
            }
            if (tid == 0) {
                out_ant[i * KA + k]  = (float)bi;
                out_mask[i * KA + k] = (bi < i) ? 1.0f : 0.0f;
                out_sc[i * KA + k]   = bv;
                sv[bi] = -CUDART_INF_F;
            }
        }
        __syncthreads();
    }
}

// -----------------------------------------------------------------------------
extern "C" void kernel_launch(void* const* d_in, const int* in_sizes, int n_in,
                              void* d_out, int out_size) {
    const float* hidden  = (const float*)d_in[0];
    const int*   starts  = (const int*)d_in[1];
    const int*   widths  = (const int*)d_in[2];
    // d_in[3] = num_top_mentions (1024), d_in[4] = num_top_antecedents (50): fixed
    const float* w_width = (const float*)d_in[5];
    const float* w_attn  = (const float*)d_in[6];
    const float* b_attn  = (const float*)d_in[7];
    const float* w_u1    = (const float*)d_in[8];
    const float* b_u1    = (const float*)d_in[9];
    const float* w_u2    = (const float*)d_in[10];
    const float* b_u2    = (const float*)d_in[11];
    const float* w_fast  = (const float*)d_in[12];
    const float* b_fast  = (const float*)d_in[13];
    float* out = (float*)d_out;

    void *p_emb = nullptr, *p_U = nullptr, *p_G = nullptr, *p_fast = nullptr;
    cudaGetSymbolAddress(&p_emb, g_span_emb);
    cudaGetSymbolAddress(&p_U, g_U);
    cudaGetSymbolAddress(&p_G, g_G);
    cudaGetSymbolAddress(&p_fast, g_fast);

    k_token_logits<<<T_TOK / 8, 256>>>(hidden, w_attn, b_attn);
    k_span_emb<<<NC, 128>>>(hidden, starts, widths, w_width);

    // mention MLP: U = relu(span_emb @ w_u1 + b_u1)   (round-7 verified path)
    k_gemm_nn<false, true, true><<<dim3(UHID / 128, NC / 128), 256>>>(
        (const float*)p_emb, w_u1, b_u1, (float*)p_U, NC, UHID, DSPAN, nullptr);
    k_mention_score<<<NC, 128>>>(w_u2, b_u2);

    k_sort<<<1, 1024>>>();
    k_greedy<<<1, 32>>>(starts, widths);
    k_compact<<<1, 1024>>>(out);

    // G = top_emb @ w_fast + b_fast   (Kahan-compensated fp32)
    k_gemm_g_kahan<<<dim3((DSPAN + 63) / 64, NM / 64), 256>>>(
        (const float*)p_emb, w_fast, b_fast, (float*)p_G);

    // fast = (tm_i + tm_j) + G @ top_emb^T  (Kahan; masked -> exact -1e30f)
    k_gemm_fast_kahan<<<dim3(NM / 64, NM / 64), 256>>>(
        (const float*)p_G, (const float*)p_emb, (float*)p_fast);

    k_topk<<<NM, 256>>>(out);
    (void)in_sizes; (void)n_in; (void)out_size;
}

// round 16
// speedup vs baseline: 1.1148x; 1.1148x over previous
#include <cuda_runtime.h>
#include <math_constants.h>
#include <math.h>

// Problem constants (fixed shapes per reference)
#define T_TOK 4096
#define NC    4096            // span candidates
#define HD    1024            // hidden
#define WMAX  30
#define META  20
#define DSPAN 3092            // 3*HD + META
#define UHID  1024
#define NM    1024            // num_top_mentions
#define KA    50              // num_top_antecedents
#define NEGF  (-1e30f)

// ---------------- scratch (static device memory; no allocations) -------------
__device__ float g_tok_logits[T_TOK];
__device__ float g_span_emb[(size_t)NC * DSPAN];   // 50.6 MB
__device__ float g_U[(size_t)NC * UHID];           // 16.8 MB
__device__ float g_scores[NC];
__device__ int   g_order[NC];
__device__ int   g_sel[NC];
__device__ int   g_top_idx[NM];
__device__ float g_top_m[NM];
__device__ float g_G[(size_t)NM * DSPAN];          // 12.7 MB
__device__ float g_fast[(size_t)NM * NM];          // 4.2 MB

// ---- packed f32x2 helpers (sm_103a). Lane-wise IEEE rn => bit-identical to
// the scalar _rn chains these replace. ------------------------------------
typedef unsigned long long ull;
__device__ __forceinline__ ull p2(float lo, float hi) {
    ull r;
    asm("mov.b64 %0, {%1, %2};" : "=l"(r) : "r"(__float_as_uint(lo)), "r"(__float_as_uint(hi)));
    return r;
}
__device__ __forceinline__ ull mul2(ull a, ull b) {
    ull r; asm("mul.rn.f32x2 %0, %1, %2;" : "=l"(r) : "l"(a), "l"(b)); return r;
}
__device__ __forceinline__ ull add2(ull a, ull b) {
    ull r; asm("add.rn.f32x2 %0, %1, %2;" : "=l"(r) : "l"(a), "l"(b)); return r;
}
__device__ __forceinline__ ull sub2(ull a, ull b) {
    ull r; asm("sub.rn.f32x2 %0, %1, %2;" : "=l"(r) : "l"(a), "l"(b)); return r;
}
__device__ __forceinline__ void fma2acc(ull& d, ull a, ull b) {
    asm("fma.rn.f32x2 %0, %1, %2, %0;" : "+l"(d) : "l"(a), "l"(b));
}
__device__ __forceinline__ float lo2(ull v) { return __uint_as_float((unsigned)(v & 0xffffffffull)); }
__device__ __forceinline__ float hi2(ull v) { return __uint_as_float((unsigned)(v >> 32)); }

// ======================= OUTPUT-0 PIPELINE (verified exact R15) ==============

// ---------------- token logits: hidden @ w_attn + b_attn ---------------------
__global__ void k_token_logits(const float* __restrict__ hidden,
                               const float* __restrict__ w_attn,
                               const float* __restrict__ b_attn) {
    int warp = (blockIdx.x * blockDim.x + threadIdx.x) >> 5;
    int lane = threadIdx.x & 31;
    if (warp >= T_TOK) return;
    const float* row = hidden + (size_t)warp * HD;
    float acc = 0.f;
    for (int j = lane; j < HD; j += 32) acc += row[j] * w_attn[j];
    #pragma unroll
    for (int off = 16; off; off >>= 1) acc += __shfl_xor_sync(0xffffffffu, acc, off);
    if (lane == 0) g_tok_logits[warp] = acc + b_attn[0];
}

// -------- span embeddings: [h_start | h_end | width_emb | attended] ----------
__global__ void k_span_emb(const float* __restrict__ hidden,
                           const int* __restrict__ starts,
                           const int* __restrict__ widths,
                           const float* __restrict__ w_width) {
    int c = blockIdx.x;
    int s = starts[c], w = widths[c];
    int e = s + w, L = w + 1;            // span length <= 30
    __shared__ float wts[32];
    int tid = threadIdx.x;               // 128 threads
    if (tid < 32) {
        float l = (tid < L) ? g_tok_logits[s + tid] : -CUDART_INF_F;
        float mx = l;
        #pragma unroll
        for (int off = 16; off; off >>= 1) mx = fmaxf(mx, __shfl_xor_sync(0xffffffffu, mx, off));
        float p = (tid < L) ? expf(l - mx) : 0.f;
        float sum = p;
        #pragma unroll
        for (int off = 16; off; off >>= 1) sum += __shfl_xor_sync(0xffffffffu, sum, off);
        wts[tid] = p / sum;
    }
    __syncthreads();

    const float4* hs = (const float4*)(hidden + (size_t)s * HD);
    const float4* he = (const float4*)(hidden + (size_t)e * HD);
    float4 a0 = make_float4(0.f, 0.f, 0.f, 0.f), a1 = a0;
    for (int t = 0; t < L; t++) {
        float wt = wts[t];
        const float4* hr = (const float4*)(hidden + (size_t)(s + t) * HD);
        float4 v0 = hr[tid], v1 = hr[tid + 128];
        a0.x += wt * v0.x; a0.y += wt * v0.y; a0.z += wt * v0.z; a0.w += wt * v0.w;
        a1.x += wt * v1.x; a1.y += wt * v1.y; a1.z += wt * v1.z; a1.w += wt * v1.w;
    }
    float* out = g_span_emb + (size_t)c * DSPAN;
    ((float4*)out)[tid]            = hs[tid];
    ((float4*)out)[tid + 128]      = hs[tid + 128];
    ((float4*)(out + HD))[tid]       = he[tid];
    ((float4*)(out + HD))[tid + 128] = he[tid + 128];
    if (tid < META) out[2 * HD + tid] = w_width[w * META + tid];
    ((float4*)(out + 2 * HD + META))[tid]       = a0;
    ((float4*)(out + 2 * HD + META))[tid + 128] = a1;
}

// ------- mention MLP GEMM (NN): packed FFMA2 inner loop (bit-identical) ------
template<bool RELU, bool BIAS>
__global__ __launch_bounds__(256) void k_gemm_nn(
    const float* __restrict__ A, const float* __restrict__ B,
    const float* __restrict__ bias, float* __restrict__ Cmat,
    int Mdim, int Ndim, int Kdim) {
    __shared__ __align__(16) float As[8][128];
    __shared__ __align__(16) float Bs[8][128];
    int tid = threadIdx.x;
    int m0 = blockIdx.y * 128, n0 = blockIdx.x * 128;
    int tx = tid & 15, ty = tid >> 4;
    ull acc2[8][4];
    #pragma unroll
    for (int i = 0; i < 8; i++)
        #pragma unroll
        for (int j = 0; j < 4; j++) acc2[i][j] = 0ull;

    int arow = tid >> 1, aq = (tid & 1) * 4;
    int bk = tid >> 5, bq = (tid & 31) * 4;
    const float* Aptr = A + (size_t)(m0 + arow) * Kdim;
    for (int k0 = 0; k0 < Kdim; k0 += 8) {
        float4 av = make_float4(0.f, 0.f, 0.f, 0.f);
        if ((k0 + aq) < Kdim) av = *(const float4*)(Aptr + k0 + aq);
        As[aq + 0][arow] = av.x; As[aq + 1][arow] = av.y;
        As[aq + 2][arow] = av.z; As[aq + 3][arow] = av.w;
        float4 bv = make_float4(0.f, 0.f, 0.f, 0.f);
        if ((k0 + bk) < Kdim)
            bv = *(const float4*)(B + (size_t)(k0 + bk) * Ndim + n0 + bq);
        *(float4*)&Bs[bk][bq] = bv;
        __syncthreads();
        #pragma unroll
        for (int kk = 0; kk < 8; kk++) {
            float a[8];
            *(float4*)(a)     = *(const float4*)&As[kk][ty * 8];
            *(float4*)(a + 4) = *(const float4*)&As[kk][ty * 8 + 4];
            ull b2[4];
            const ull* bp = (const ull*)&Bs[kk][tx * 8];
            b2[0] = bp[0]; b2[1] = bp[1]; b2[2] = bp[2]; b2[3] = bp[3];
            #pragma unroll
            for (int i = 0; i < 8; i++) {
                ull aa = p2(a[i], a[i]);
                #pragma unroll
                for (int j = 0; j < 4; j++) fma2acc(acc2[i][j], aa, b2[j]);
            }
        }
        __syncthreads();
    }
    #pragma unroll
    for (int i = 0; i < 8; i++) {
        int r = m0 + ty * 8 + i;
        #pragma unroll
        for (int j = 0; j < 4; j++) {
            int cc0 = n0 + tx * 8 + 2 * j;
            float v0 = lo2(acc2[i][j]);
            float v1 = hi2(acc2[i][j]);
            if (BIAS) { v0 += bias[cc0]; v1 += bias[cc0 + 1]; }
            if (RELU) { v0 = fmaxf(v0, 0.f); v1 = fmaxf(v1, 0.f); }
            Cmat[(size_t)r * Ndim + cc0]     = v0;
            Cmat[(size_t)r * Ndim + cc0 + 1] = v1;
        }
    }
}

// -------- mention scores: dot(relu'd U row, w_u2) + b_u2 ---------------------
__global__ void k_mention_score(const float* __restrict__ w_u2,
                                const float* __restrict__ b_u2) {
    int c = blockIdx.x;
    int tid = threadIdx.x;   // 128 threads
    const float* row = g_U + (size_t)c * UHID;
    float acc = 0.f;
    for (int j = tid; j < UHID; j += 128) acc += row[j] * w_u2[j];
    #pragma unroll
    for (int off = 16; off; off >>= 1) acc += __shfl_xor_sync(0xffffffffu, acc, off);
    __shared__ float rs[4];
    if ((tid & 31) == 0) rs[tid >> 5] = acc;
    __syncthreads();
    if (tid == 0) g_scores[c] = rs[0] + rs[1] + rs[2] + rs[3] + b_u2[0];
}

// -------- bitonic argsort (descending score, ties -> lower index first) ------
__global__ void k_sort() {
    __shared__ float sv[NC];
    __shared__ int   si[NC];
    int tid = threadIdx.x;   // 1024
    for (int i = tid; i < NC; i += 1024) { sv[i] = g_scores[i]; si[i] = i; }
    __syncthreads();
    for (int k = 2; k <= NC; k <<= 1) {
        for (int j = k >> 1; j > 0; j >>= 1) {
            for (int i = tid; i < NC; i += 1024) {
                int ixj = i ^ j;
                if (ixj > i) {
                    bool dir = ((i & k) == 0);
                    float v1 = sv[i], v2 = sv[ixj];
                    int a1 = si[i], a2 = si[ixj];
                    bool i_later = (v1 < v2) || (v1 == v2 && a1 > a2);
                    if (i_later == dir) {
                        sv[i] = v2; si[i] = a2; sv[ixj] = v1; si[ixj] = a1;
                    }
                }
            }
            __syncthreads();
        }
    }
    for (int i = tid; i < NC; i += 1024) g_order[i] = si[i];
}

// -------- greedy non-crossing selection (single warp, early break) -----------
__global__ void k_greedy(const int* __restrict__ starts,
                         const int* __restrict__ widths) {
    __shared__ int le[T_TOK];   // latest_end
    __shared__ int es[T_TOK];   // earliest_start
    int lane = threadIdx.x;     // 32 threads
    for (int i = lane; i < T_TOK; i += 32) { le[i] = -1; es[i] = T_TOK; }
    for (int i = lane; i < NC; i += 32) g_sel[i] = 0;
    __syncwarp();
    int count = 0;
    for (int it = 0; it < NC; it++) {
        int ind = g_order[it];
        int s = starts[ind];
        int span = widths[ind];          // = e - s, 0..29
        int e = s + span;
        bool bad = false;
        if (lane < span) {
            if (le[s + 1 + lane] > e) bad = true;   // cross1 over (s, e]
            if (es[s + lane] < s)     bad = true;   // cross2 over [s, e)
        }
        unsigned anyb = __ballot_sync(0xffffffffu, bad);
        if (anyb == 0u) {
            if (lane == 0) {
                le[s] = max(le[s], e);
                es[e] = min(es[e], s);
                g_sel[ind] = 1;
            }
            count++;
            if (count == NM) break;
        }
        __syncwarp();
    }
}

// -------- compaction: selected indices ascending -> top_idx, top_m, out ------
__global__ void k_compact(float* __restrict__ out) {
    __shared__ int ps[1024];
    int tid = threadIdx.x;   // 1024
    int c4 = tid * 4;
    int f0 = g_sel[c4], f1 = g_sel[c4 + 1], f2 = g_sel[c4 + 2], f3 = g_sel[c4 + 3];
    int s = f0 + f1 + f2 + f3;
    ps[tid] = s;
    __syncthreads();
    for (int off = 1; off < 1024; off <<= 1) {
        int add = (tid >= off) ? ps[tid - off] : 0;
        __syncthreads();
        ps[tid] += add;
        __syncthreads();
    }
    int total = ps[1023];
    int pos = ps[tid] - s;
    if (f0) { if (pos < NM) g_top_idx[pos] = c4;     pos++; }
    if (f1) { if (pos < NM) g_top_idx[pos] = c4 + 1; pos++; }
    if (f2) { if (pos < NM) g_top_idx[pos] = c4 + 2; pos++; }
    if (f3) { if (pos < NM) g_top_idx[pos] = c4 + 3; pos++; }
    __syncthreads();
    if (tid >= total && tid < NM) g_top_idx[tid] = NC - 1;  // pad -> 4095
    __syncthreads();
    int ti = g_top_idx[tid];
    g_top_m[tid] = g_scores[ti];
    out[tid] = (float)ti;
}

// ================== DOWNSTREAM GEMMS: packed Kahan fp32 ======================
// Same Kahan algebra as the R15-verified kernels, but two accumulator lanes per
// 64-bit register via f32x2 ops (lane-wise rn => bit-identical per lane).

// G = emb[top_idx] @ w_fast + b_fast.  64x64 tile, 256 thr, 4x4/thread.
__global__ __launch_bounds__(256) void k_gemm_g_kahan(
    const float* __restrict__ Afull /*span_emb*/, const float* __restrict__ B /*w_fast*/,
    const float* __restrict__ bias, float* __restrict__ Cmat /*G*/) {
    const int Kdim = DSPAN, Ndim = DSPAN;
    __shared__ __align__(16) float As[8][64];
    __shared__ __align__(16) float Bs[8][64];
    int tid = threadIdx.x;
    int m0 = blockIdx.y * 64, n0 = blockIdx.x * 64;
    int tx = tid & 15, ty = tid >> 4;
    ull s2[4][2], c2[4][2];
    #pragma unroll
    for (int i = 0; i < 4; i++)
        #pragma unroll
        for (int j = 0; j < 2; j++) { s2[i][j] = 0ull; c2[i][j] = 0ull; }

    for (int k0 = 0; k0 < Kdim; k0 += 8) {
        #pragma unroll
        for (int i = tid; i < 512; i += 256) {
            int kk = i & 7, m = i >> 3;
            int src = g_top_idx[m0 + m];
            float v = 0.f;
            if (k0 + kk < Kdim) v = Afull[(size_t)src * Kdim + k0 + kk];
            As[kk][m] = v;
        }
        #pragma unroll
        for (int i = tid; i < 512; i += 256) {
            int kk = i >> 6, nn = i & 63;
            float v = 0.f;
            if (k0 + kk < Kdim && n0 + nn < Ndim)
                v = B[(size_t)(k0 + kk) * Ndim + n0 + nn];
            Bs[kk][nn] = v;
        }
        __syncthreads();
        #pragma unroll
        for (int kk = 0; kk < 8; kk++) {
            float a[4];
            #pragma unroll
            for (int i = 0; i < 4; i++) a[i] = As[kk][ty * 4 + i];
            ull b2[2];
            const ull* bp = (const ull*)&Bs[kk][tx * 4];
            b2[0] = bp[0]; b2[1] = bp[1];
            #pragma unroll
            for (int i = 0; i < 4; i++) {
                ull aa = p2(a[i], a[i]);
                #pragma unroll
                for (int j = 0; j < 2; j++) {
                    ull prod = mul2(aa, b2[j]);
                    ull y = sub2(prod, c2[i][j]);
                    ull t = add2(s2[i][j], y);
                    c2[i][j] = sub2(sub2(t, s2[i][j]), y);
                    s2[i][j] = t;
                }
            }
        }
        __syncthreads();
    }
    #pragma unroll
    for (int i = 0; i < 4; i++) {
        int r = m0 + ty * 4 + i;
        #pragma unroll
        for (int j = 0; j < 2; j++) {
            int cc0 = n0 + tx * 4 + 2 * j;
            float d0 = __fadd_rn(lo2(s2[i][j]), lo2(c2[i][j]));
            float d1 = __fadd_rn(hi2(s2[i][j]), hi2(c2[i][j]));
            if (cc0 < Ndim)     Cmat[(size_t)r * Ndim + cc0]     = __fadd_rn(d0, bias[cc0]);
            if (cc0 + 1 < Ndim) Cmat[(size_t)r * Ndim + cc0 + 1] = __fadd_rn(d1, bias[cc0 + 1]);
        }
    }
}

// fast = (tm_i + tm_j) + G @ emb[top_idx]^T, masked (cc>=r) -> exact -1e30f.
__global__ __launch_bounds__(256) void k_gemm_fast_kahan(
    const float* __restrict__ A /*G*/, const float* __restrict__ Bfull /*span_emb*/,
    float* __restrict__ Cmat /*fast*/) {
    const int Kdim = DSPAN;
    __shared__ __align__(16) float As[8][64];
    __shared__ __align__(16) float Bs[8][64];
    int tid = threadIdx.x;
    int m0 = blockIdx.y * 64, n0 = blockIdx.x * 64;
    int tx = tid & 15, ty = tid >> 4;
    ull s2[4][2], c2[4][2];
    #pragma unroll
    for (int i = 0; i < 4; i++)
        #pragma unroll
        for (int j = 0; j < 2; j++) { s2[i][j] = 0ull; c2[i][j] = 0ull; }

    for (int k0 = 0; k0 < Kdim; k0 += 8) {
        #pragma unroll
        for (int i = tid; i < 512; i += 256) {
            int kk = i & 7, m = i >> 3;
            float v = 0.f;
            if (k0 + kk < Kdim) v = A[(size_t)(m0 + m) * Kdim + k0 + kk];
            As[kk][m] = v;
        }
        #pragma unroll
        for (int i = tid; i < 512; i += 256) {
            int kk = i & 7, nn = i >> 3;
            int src = g_top_idx[n0 + nn];
            float v = 0.f;
            if (k0 + kk < Kdim) v = Bfull[(size_t)src * Kdim + k0 + kk];
            Bs[kk][nn] = v;
        }
        __syncthreads();
        #pragma unroll
        for (int kk = 0; kk < 8; kk++) {
            float a[4];
            #pragma unroll
            for (int i = 0; i < 4; i++) a[i] = As[kk][ty * 4 + i];
            ull b2[2];
            const ull* bp = (const ull*)&Bs[kk][tx * 4];
            b2[0] = bp[0]; b2[1] = bp[1];
            #pragma unroll
            for (int i = 0; i < 4; i++) {
                ull aa = p2(a[i], a[i]);
                #pragma unroll
                for (int j = 0; j < 2; j++) {
                    ull prod = mul2(aa, b2[j]);
                    ull y = sub2(prod, c2[i][j]);
                    ull t = add2(s2[i][j], y);
                    c2[i][j] = sub2(sub2(t, s2[i][j]), y);
                    s2[i][j] = t;
                }
            }
        }
        __syncthreads();
    }
    #pragma unroll
    for (int i = 0; i < 4; i++) {
        int r = m0 + ty * 4 + i;
        float tmr = g_top_m[r];
        #pragma unroll
        for (int j = 0; j < 2; j++) {
            int cc0 = n0 + tx * 4 + 2 * j;
            float d0 = __fadd_rn(lo2(s2[i][j]), lo2(c2[i][j]));
            float d1 = __fadd_rn(hi2(s2[i][j]), hi2(c2[i][j]));
            // ref association: ((tm_i + tm_j) + 0) + dot
            float v0 = __fadd_rn(__fadd_rn(tmr, g_top_m[cc0]), d0);
            float v1 = __fadd_rn(__fadd_rn(tmr, g_top_m[cc0 + 1]), d1);
            if (cc0 >= r)     v0 = NEGF;
            if (cc0 + 1 >= r) v1 = NEGF;
            Cmat[(size_t)r * NM + cc0]     = v0;
            Cmat[(size_t)r * NM + cc0 + 1] = v1;
        }
    }
}

// -------- per-row top-50 (lax.top_k semantics: desc, ties -> lowest index) ---
__global__ void k_topk(float* __restrict__ out) {
    int i = blockIdx.x;
    __shared__ float sv[NM];
    __shared__ float wvv[8];
    __shared__ int   wii[8];
    int tid = threadIdx.x;   // 256
    const float* row = g_fast + (size_t)i * NM;
    for (int j = tid; j < NM; j += 256) sv[j] = row[j];
    __syncthreads();
    float* out_ant  = out + NM;
    float* out_mask = out + NM + NM * KA;
    float* out_sc   = out + NM + 2 * NM * KA;
    for (int k = 0; k < KA; k++) {
        float bv = -CUDART_INF_F;
        int bi = NM;
        for (int j = tid; j < NM; j += 256) {
            float v = sv[j];
            if (v > bv || (v == bv && j < bi)) { bv = v; bi = j; }
        }
        #pragma unroll
        for (int off = 16; off; off >>= 1) {
            float ov = __shfl_down_sync(0xffffffffu, bv, off);
            int   oi = __shfl_down_sync(0xffffffffu, bi, off);
            if (ov > bv || (ov == bv && oi < bi)) { bv = ov; bi = oi; }
        }
        if ((tid & 31) == 0) { wvv[tid >> 5] = bv; wii[tid >> 5] = bi; }
        __syncthreads();
        if (tid < 32) {
            bv = (tid < 8) ? wvv[tid] : -CUDART_INF_F;
            bi = (tid < 8) ? wii[tid] : NM;
            #pragma unroll
            for (int off = 4; off; off >>= 1) {
                float ov = __shfl_down_sync(0xffffffffu, bv, off);
                int   oi = __shfl_down_sync(0xffffffffu, bi, off);
                if (ov > bv || (ov == bv && oi < bi)) { bv = ov; bi = oi; }
            }
            if (tid == 0) {
                out_ant[i * KA + k]  = (float)bi;
                out_mask[i * KA + k] = (bi < i) ? 1.0f : 0.0f;
                out_sc[i * KA + k]   = bv;
                sv[bi] = -CUDART_INF_F;
            }
        }
        __syncthreads();
    }
}

// -----------------------------------------------------------------------------
extern "C" void kernel_launch(void* const* d_in, const int* in_sizes, int n_in,
                              void* d_out, int out_size) {
    const float* hidden  = (const float*)d_in[0];
    const int*   starts  = (const int*)d_in[1];
    const int*   widths  = (const int*)d_in[2];
    // d_in[3] = num_top_mentions (1024), d_in[4] = num_top_antecedents (50): fixed
    const float* w_width = (const float*)d_in[5];
    const float* w_attn  = (const float*)d_in[6];
    const float* b_attn  = (const float*)d_in[7];
    const float* w_u1    = (const float*)d_in[8];
    const float* b_u1    = (const float*)d_in[9];
    const float* w_u2    = (const float*)d_in[10];
    const float* b_u2    = (const float*)d_in[11];
    const float* w_fast  = (const float*)d_in[12];
    const float* b_fast  = (const float*)d_in[13];
    float* out = (float*)d_out;

    void *p_emb = nullptr, *p_U = nullptr, *p_G = nullptr, *p_fast = nullptr;
    cudaGetSymbolAddress(&p_emb, g_span_emb);
    cudaGetSymbolAddress(&p_U, g_U);
    cudaGetSymbolAddress(&p_G, g_G);
    cudaGetSymbolAddress(&p_fast, g_fast);

    k_token_logits<<<T_TOK / 8, 256>>>(hidden, w_attn, b_attn);
    k_span_emb<<<NC, 128>>>(hidden, starts, widths, w_width);

    // mention MLP: U = relu(span_emb @ w_u1 + b_u1)   (packed FFMA2, bit-identical)
    k_gemm_nn<true, true><<<dim3(UHID / 128, NC / 128), 256>>>(
        (const float*)p_emb, w_u1, b_u1, (float*)p_U, NC, UHID, DSPAN);
    k_mention_score<<<NC, 128>>>(w_u2, b_u2);

    k_sort<<<1, 1024>>>();
    k_greedy<<<1, 32>>>(starts, widths);
    k_compact<<<1, 1024>>>(out);

    // G = top_emb @ w_fast + b_fast   (packed Kahan fp32)
    k_gemm_g_kahan<<<dim3((DSPAN + 63) / 64, NM / 64), 256>>>(
        (const float*)p_emb, w_fast, b_fast, (float*)p_G);

    // fast = (tm_i + tm_j) + G @ top_emb^T  (packed Kahan; masked -> -1e30f)
    k_gemm_fast_kahan<<<dim3(NM / 64, NM / 64), 256>>>(
        (const float*)p_G, (const float*)p_emb, (float*)p_fast);

    k_topk<<<NM, 256>>>(out);
    (void)in_sizes; (void)n_in; (void)out_size;
}